// round 4
// baseline (speedup 1.0000x reference)
#include <cuda_runtime.h>

#define EPS 1e-9f
#define MAX_NODES 200000
#define EDGE_BLOCKS 1184   // 8 blocks/SM * 148 SMs
#define TPB 256

// Per-node (x, y) table: 1.6 MB, lives in L2 after the node kernel writes it.
__device__ float2 g_xy[MAX_NODES];
// Per-block partial sums (no init needed: every used slot is written each call).
__device__ double g_edge_partial[2048];
__device__ double g_node_partial[1024];
// Self-resetting last-block-done counter (atomicInc wraps back to 0).
__device__ unsigned g_done = 0;

__device__ __forceinline__ double block_reduce_add(double v) {
    __shared__ double s[32];
    int lane = threadIdx.x & 31;
    int wid  = threadIdx.x >> 5;
#pragma unroll
    for (int o = 16; o > 0; o >>= 1) v += __shfl_down_sync(0xffffffffu, v, o);
    if (lane == 0) s[wid] = v;
    __syncthreads();
    int nw = (blockDim.x + 31) >> 5;
    v = (threadIdx.x < nw) ? s[threadIdx.x] : 0.0;
    if (wid == 0) {
#pragma unroll
        for (int o = 16; o > 0; o >>= 1) v += __shfl_down_sync(0xffffffffu, v, o);
    }
    __syncthreads();   // allow back-to-back reuse of the shared scratch
    return v;
}

// Extract (x, y) per node, store packed table, and compute compactness term:
// quad(p, origin) = (1 - aa) / safe(aa) with aa = 1 - x^2 - y^2.
__global__ void node_kernel(const float* __restrict__ z, int n) {
    int i = blockIdx.x * blockDim.x + threadIdx.x;
    double local = 0.0;
    if (i < n) {
        float2 xy = *reinterpret_cast<const float2*>(z + (size_t)i * 128);
        g_xy[i] = xy;
        float aa   = 1.0f - (xy.x * xy.x + xy.y * xy.y);
        float num  = 1.0f - aa;
        float safe = copysignf(fmaxf(fabsf(aa), EPS), aa);
        local = (double)(num / safe);
    }
    double bs = block_reduce_add(local);
    if (threadIdx.x == 0) g_node_partial[blockIdx.x] = bs;
}

// Per-edge numerator and clamped denominator of the quadrance.
__device__ __forceinline__ void edge_nd(float2 a, float2 b, float& num, float& safe) {
    float aa = 1.0f - (a.x * a.x + a.y * a.y);
    float bb = 1.0f - (b.x * b.x + b.y * b.y);
    float ab = 1.0f - (a.x * b.x + a.y * b.y);
    float p  = aa * bb;
    num  = ab * ab - p;
    safe = copysignf(fmaxf(fabsf(p), EPS), p);
}

// 4-edge group: gathers already in registers; Montgomery batch inversion
// (one fp32 division serves 4 edges -> 4x fewer MUFU.RCP).
// |d_i| >= EPS=1e-9 so the 4-way product (>=1e-36) stays normal in fp32.
__device__ __forceinline__ double quad4(float2 a0, float2 b0, float2 a1, float2 b1,
                                        float2 a2, float2 b2, float2 a3, float2 b3) {
    float n0, n1, n2, n3, d0, d1, d2, d3;
    edge_nd(a0, b0, n0, d0);
    edge_nd(a1, b1, n1, d1);
    edge_nd(a2, b2, n2, d2);
    edge_nd(a3, b3, n3, d3);
    float t01   = d0 * d1;
    float t012  = t01 * d2;
    float t0123 = t012 * d3;
    float r     = 1.0f / t0123;
    float inv3  = r * t012;
    float r012  = r * d3;
    float inv2  = r012 * t01;
    float r01   = r012 * d2;
    float inv1  = r01 * d0;
    float inv0  = r01 * d1;
    return (double)(n0 * inv0) + (double)(n1 * inv1)
         + (double)(n2 * inv2) + (double)(n3 * inv3);
}

// Persistent-grid edge kernel: 8 edges/thread/iter (16 outstanding L2 gathers),
// per-block partials, and the last block performs the full finalize.
__global__ void __launch_bounds__(TPB) edge_kernel(
        const int* __restrict__ src, const int* __restrict__ dst,
        float* __restrict__ out, int n_edges, int n_nodes, int node_blocks) {
    const float2* __restrict__ xy = g_xy;
    const int4*   __restrict__ src4 = reinterpret_cast<const int4*>(src);
    const int4*   __restrict__ dst4 = reinterpret_cast<const int4*>(dst);

    int ngroups = n_edges >> 3;          // 8 edges per group
    int stride  = gridDim.x * blockDim.x;
    double local = 0.0;

    for (int g = blockIdx.x * blockDim.x + threadIdx.x; g < ngroups; g += stride) {
        int4 s0 = src4[2 * g], s1 = src4[2 * g + 1];
        int4 d0 = dst4[2 * g], d1 = dst4[2 * g + 1];
        float2 a0 = __ldg(&xy[s0.x]), b0 = __ldg(&xy[d0.x]);
        float2 a1 = __ldg(&xy[s0.y]), b1 = __ldg(&xy[d0.y]);
        float2 a2 = __ldg(&xy[s0.z]), b2 = __ldg(&xy[d0.z]);
        float2 a3 = __ldg(&xy[s0.w]), b3 = __ldg(&xy[d0.w]);
        float2 a4 = __ldg(&xy[s1.x]), b4 = __ldg(&xy[d1.x]);
        float2 a5 = __ldg(&xy[s1.y]), b5 = __ldg(&xy[d1.y]);
        float2 a6 = __ldg(&xy[s1.z]), b6 = __ldg(&xy[d1.z]);
        float2 a7 = __ldg(&xy[s1.w]), b7 = __ldg(&xy[d1.w]);

        local += quad4(a0, b0, a1, b1, a2, b2, a3, b3);
        local += quad4(a4, b4, a5, b5, a6, b6, a7, b7);
    }

    double bs = block_reduce_add(local);
    __shared__ bool is_last;
    if (threadIdx.x == 0) {
        g_edge_partial[blockIdx.x] = bs;
        __threadfence();
        unsigned old = atomicInc(&g_done, gridDim.x - 1);
        is_last = (old == gridDim.x - 1);
    }
    __syncthreads();
    if (!is_last) return;

    // ---- finalize (runs in exactly one block per call) ----
    int tid = threadIdx.x;

    double esum = 0.0;
    for (int i = tid; i < (int)gridDim.x; i += blockDim.x) esum += g_edge_partial[i];
    esum = block_reduce_add(esum);

    double nsum = 0.0;
    for (int i = tid; i < node_blocks; i += blockDim.x) nsum += g_node_partial[i];
    nsum = block_reduce_add(nsum);

    // tail edges (if E % 8 != 0)
    double tailsum = 0.0;
    for (int e = ngroups * 8 + tid; e < n_edges; e += blockDim.x) {
        float2 a = xy[src[e]], b = xy[dst[e]];
        float num, safe;
        edge_nd(a, b, num, safe);
        tailsum += (double)(num / safe);
    }
    tailsum = block_reduce_add(tailsum);

    // spread over first min(10, E) edges on lines l = cross([x,y,1],[0,0,1]) = (y,-x,0)
    int nsp = n_edges < 10 ? n_edges : 10;
    double sp = 0.0;
    if (tid < nsp) {
        float2 a = xy[src[tid]], b = xy[dst[tid]];
        float laa = -(a.x * a.x + a.y * a.y);
        float lbb = -(b.x * b.x + b.y * b.y);
        float lab = -(a.x * b.x + a.y * b.y);
        float p   = laa * lbb;
        float num = lab * lab - p;
        float safe = copysignf(fmaxf(fabsf(p), EPS), p);
        sp = (double)(num / safe);
    }
    sp = block_reduce_add(sp);

    if (tid == 0) {
        double prox   = (esum + tailsum) / (double)n_edges;
        double comp   = nsum / (double)n_nodes;
        double spread = (nsp > 0) ? (sp / (double)nsp) : 0.0;
        out[0] = (float)(prox + comp + 0.1 * spread);
    }
}

extern "C" void kernel_launch(void* const* d_in, const int* in_sizes, int n_in,
                              void* d_out, int out_size) {
    const float* z  = (const float*)d_in[0];
    const int*   ei = (const int*)d_in[1];
    int n_nodes = in_sizes[0] / 128;
    int n_edges = in_sizes[1] / 2;
    const int* src = ei;
    const int* dst = ei + n_edges;

    int node_blocks = (n_nodes + TPB - 1) / TPB;
    node_kernel<<<node_blocks, TPB>>>(z, n_nodes);
    edge_kernel<<<EDGE_BLOCKS, TPB>>>(src, dst, (float*)d_out,
                                      n_edges, n_nodes, node_blocks);
}